// round 5
// baseline (speedup 1.0000x reference)
#include <cuda_runtime.h>
#include <cstdint>

// ---------------- problem constants ----------------
#define HS      250          // sender hidden
#define HR      100          // receiver hidden
#define NV      40           // vocab (EOS = 39)
#define MAXLEN  30
#define IN_N    4096
#define OUT_N   262144

// ---------------- scratch (device globals; no allocation) ----------------
__device__ float g_h0[256];
__device__ float g_hR[112];
__device__ float g_part[1024];
__device__ float g_inv_d;

// ---------------- helpers ----------------
__device__ __forceinline__ float sigf(float x) { return 1.0f / (1.0f + expf(-x)); }

__device__ __forceinline__ uint32_t smem_u32(const void* p) {
    return (uint32_t)__cvta_generic_to_shared(p);
}

#define CLUSTER_SYNC() do {                                           \
    asm volatile("barrier.cluster.arrive.aligned;" ::: "memory");     \
    asm volatile("barrier.cluster.wait.aligned;"   ::: "memory");     \
} while (0)

// ---------------- kernel 1: h0 = relu(W_s1 @ x + b_s1) ----------------
// grid 250 blocks x 256 threads; block b computes row b (4096-dot).
__global__ void h0_kernel(const float* __restrict__ Ws1,
                          const float* __restrict__ bs1,
                          const float* __restrict__ x) {
    int row = blockIdx.x, tid = threadIdx.x;
    const float4* w  = reinterpret_cast<const float4*>(Ws1 + (size_t)row * IN_N);
    const float4* xv = reinterpret_cast<const float4*>(x);
    float acc = 0.f;
    #pragma unroll 4
    for (int i = tid; i < IN_N / 4; i += 256) {
        float4 a = w[i], b = xv[i];
        acc += a.x * b.x + a.y * b.y + a.z * b.z + a.w * b.w;
    }
    __shared__ float red[8];
    for (int o = 16; o; o >>= 1) acc += __shfl_down_sync(0xffffffffu, acc, o);
    if ((tid & 31) == 0) red[tid >> 5] = acc;
    __syncthreads();
    if (tid < 8) {
        float s = red[tid];
        for (int o = 4; o; o >>= 1) s += __shfl_down_sync(0xffu, s, o);
        if (tid == 0) g_h0[row] = fmaxf(s + bs1[row], 0.f);
    }
}

// ---------------- kernel 2: sequential sender + receiver (cluster of 8) ----
// SMEM float offsets --- sender phase:
#define OFF_WHH   0                       // 128 rows x 251 (padded)   = 32128
#define OFF_WIH   32128                   // 128 x 41                  =  5248
#define OFF_WP    37376                   // 40 x 250                  = 10000
#define OFF_BIA   47376                   // 128
#define OFF_BP    47504                   // 40
#define OFF_GUM   47544                   // 30*40 = 1200
#define OFF_HFULL 48744                   // 256
#define OFF_HPUB  49000                   // 2 x 32 (double-buffered publish)
#define OFF_CST   49064                   // 32
#define OFF_GAT   49096                   // 128
#define OFF_LOG   49224                   // 40
#define OFF_IDX   49264                   // int
// receiver phase (reuses the region; CTA0 only, after a cluster barrier):
#define OFF_WHH2  0                       // 400 x 102 (padded)        = 40800
#define OFF_UCOL  40800                   // 30 x 400                  = 12000
#define OFF_B2    52800                   // 400
#define OFF_G2    53200                   // 400
#define OFF_HR    53600                   // 112
#define OFF_CR    53712                   // 112
#define OFF_MSG   53824                   // 32 ints (outside both unions' hot zones)
#define SM_FLOATS 53856
#define SMEM_BYTES (SM_FLOATS * 4)        // 215424 B

__global__ void __cluster_dims__(8, 1, 1) __launch_bounds__(256, 1)
seq_kernel(const float* __restrict__ gumbel,
           const float* __restrict__ Wih1, const float* __restrict__ Whh1,
           const float* __restrict__ bih1, const float* __restrict__ bhh1,
           const float* __restrict__ Wp,   const float* __restrict__ bp,
           const float* __restrict__ Wih2, const float* __restrict__ Whh2,
           const float* __restrict__ bih2, const float* __restrict__ bhh2) {
    extern __shared__ float sm[];
    int* smi = reinterpret_cast<int*>(sm);
    const int tid  = threadIdx.x;
    const int rank = blockIdx.x;                  // cluster rank (grid == cluster)
    const int lane = tid & 31;
    const int wid  = tid >> 5;

    // ---- hidden-unit partition: CTA r owns hidden [32r, 32r+NH) ----
    const int NH = (rank < 7) ? 32 : (HS - 7 * 32);   // 32 or 26
    const int H0 = rank * 32;
    const int G  = 4 * NH;                            // gate rows owned (<=128)

    // ---- stage sender weights into SMEM ----
    for (int lr = 0; lr < G; ++lr) {
        int gg = lr / NH, j = lr - gg * NH;
        int grow = 250 * gg + H0 + j;                 // global gate row
        for (int k = tid; k < HS; k += 256)
            sm[OFF_WHH + lr * 251 + k] = Whh1[(size_t)grow * HS + k];
        if (tid < NV) sm[OFF_WIH + lr * 41 + tid] = Wih1[grow * NV + tid];
        if (tid == 0) sm[OFF_BIA + lr] = bih1[grow] + bhh1[grow];
    }
    for (int i = tid; i < NV * HS; i += 256) sm[OFF_WP + i] = Wp[i];
    if (tid < NV) sm[OFF_BP + tid] = bp[tid];
    for (int i = tid; i < MAXLEN * NV; i += 256) sm[OFF_GUM + i] = gumbel[i];
    if (tid < 256) sm[OFF_HFULL + tid] = (tid < HS) ? g_h0[tid] : 0.f;
    if (tid < 32)  sm[OFF_CST + tid] = 0.f;
    __syncthreads();

    // ---- sender loop ----
    int idx_prev = -1;
    int parity   = 0;
    int Lmsg     = 0;

    for (int t = 0; t < MAXLEN; ++t) {
        // gates: 2 threads per row (column halves), shuffle combine
        {
            int row = tid >> 1, half = tid & 1;
            float acc = 0.f;
            const float* wr = &sm[OFF_WHH + row * 251 + half * 125];
            const float* hf = &sm[OFF_HFULL + half * 125];
            #pragma unroll 5
            for (int k = 0; k < 125; ++k) acc += wr[k] * hf[k];
            acc += __shfl_xor_sync(0xffffffffu, acc, 1);
            if (half == 0 && row < G) {
                acc += sm[OFF_BIA + row];
                if (idx_prev >= 0) acc += sm[OFF_WIH + row * 41 + idx_prev];
                sm[OFF_GAT + row] = acc;
            }
        }
        __syncthreads();
        // per-hidden LSTM update, publish new h slice
        if (tid < NH) {
            float gi = sm[OFF_GAT + tid];
            float gf = sm[OFF_GAT + NH + tid];
            float gz = sm[OFF_GAT + 2 * NH + tid];
            float go = sm[OFF_GAT + 3 * NH + tid];
            float c  = sm[OFF_CST + tid];
            float cn = sigf(gf) * c + sigf(gi) * tanhf(gz);
            float hn = sigf(go) * tanhf(cn);
            sm[OFF_CST + tid] = cn;
            sm[OFF_HPUB + parity * 32 + tid] = hn;
        }
        CLUSTER_SYNC();
        // gather full new h from all 8 CTAs (DSMEM)
        if (tid < HS) {
            int owner = tid >> 5, loc = tid & 31;
            uint32_t la = smem_u32(&sm[OFF_HPUB + parity * 32 + loc]);
            uint32_t ra;
            asm("mapa.shared::cluster.u32 %0, %1, %2;" : "=r"(ra) : "r"(la), "r"(owner));
            float v;
            asm volatile("ld.shared::cluster.f32 %0, [%1];" : "=f"(v) : "r"(ra));
            sm[OFF_HFULL + tid] = v;
        }
        __syncthreads();
        // logits (replicated in every CTA): warp-per-row strided dots
        for (int rr = wid; rr < NV; rr += 8) {
            float a = 0.f;
            for (int k = lane; k < HS; k += 32)
                a += sm[OFF_WP + rr * HS + k] * sm[OFF_HFULL + k];
            for (int o = 16; o; o >>= 1) a += __shfl_down_sync(0xffffffffu, a, o);
            if (lane == 0)
                sm[OFF_LOG + rr] = a + sm[OFF_BP + rr] + sm[OFF_GUM + t * NV + rr];
        }
        __syncthreads();
        // argmax over 40 (first-max tie-break, matching jnp.argmax)
        if (wid == 0) {
            float v = sm[OFF_LOG + lane];
            int bi = lane;
            if (lane < NV - 32) {
                float v2 = sm[OFF_LOG + 32 + lane];
                if (v2 > v) { v = v2; bi = 32 + lane; }
            }
            for (int o = 16; o; o >>= 1) {
                float ov = __shfl_down_sync(0xffffffffu, v, o);
                int   oi = __shfl_down_sync(0xffffffffu, bi, o);
                if (ov > v || (ov == v && oi < bi)) { v = ov; bi = oi; }
            }
            if (lane == 0) smi[OFF_IDX] = bi;
        }
        __syncthreads();
        int idx = smi[OFF_IDX];
        bool last = (t == MAXLEN - 1);
        if (rank == 0 && tid == 0) smi[OFF_MSG + t] = last ? (NV - 1) : idx;
        if (idx == NV - 1 || last) { Lmsg = t + 1; break; }
        idx_prev = idx;
        parity ^= 1;
    }

    // All CTAs must pass this barrier before CTA0 reuses SMEM (otherwise a
    // slow peer's final DSMEM gather races the receiver's overwrites).
    CLUSTER_SYNC();
    if (rank != 0) return;

    // ---- receiver (CTA0 only): stage W_hh2 + per-step input columns ----
    for (int i = tid; i < 400 * HR; i += 256) {
        int row = i / HR, k = i - row * HR;
        sm[OFF_WHH2 + row * 102 + k] = Whh2[i];
    }
    for (int i = tid; i < 400; i += 256) sm[OFF_B2 + i] = bih2[i] + bhh2[i];
    __syncthreads();   // MSG visible to all threads before ucol gather
    for (int i = tid; i < Lmsg * 400; i += 256) {
        int tt = i / 400, row = i - tt * 400;
        sm[OFF_UCOL + i] = Wih2[row * NV + smi[OFF_MSG + tt]];
    }
    if (tid < 112) { sm[OFF_HR + tid] = 0.f; sm[OFF_CR + tid] = 0.f; }
    __syncthreads();

    for (int t = 0; t < Lmsg; ++t) {
        for (int row = tid; row < 400; row += 256) {
            float acc = sm[OFF_B2 + row] + sm[OFF_UCOL + t * 400 + row];
            const float2* wr2 = reinterpret_cast<const float2*>(&sm[OFF_WHH2 + row * 102]);
            const float2* h2  = reinterpret_cast<const float2*>(&sm[OFF_HR]);
            #pragma unroll 5
            for (int k = 0; k < HR / 2; ++k) {
                float2 a = wr2[k], b = h2[k];
                acc += a.x * b.x + a.y * b.y;
            }
            sm[OFF_G2 + row] = acc;
        }
        __syncthreads();
        if (tid < HR) {
            float gi = sm[OFF_G2 + tid];
            float gf = sm[OFF_G2 + HR + tid];
            float gz = sm[OFF_G2 + 2 * HR + tid];
            float go = sm[OFF_G2 + 3 * HR + tid];
            float c  = sm[OFF_CR + tid];
            float cn = sigf(gf) * c + sigf(gi) * tanhf(gz);
            sm[OFF_CR + tid] = cn;
            sm[OFF_HR + tid] = sigf(go) * tanhf(cn);
        }
        __syncthreads();
    }
    if (tid < HR) g_hR[tid] = sm[OFF_HR + tid];
}

// ---------------- kernel 3: logits -> exp, per-block partial sums ----------
__global__ void __launch_bounds__(256)
out_kernel(const float* __restrict__ Wr, const float* __restrict__ br,
           float* __restrict__ out) {
    __shared__ float h[HR];
    __shared__ float red[8];
    int tid = threadIdx.x;
    if (tid < HR) h[tid] = g_hR[tid];
    __syncthreads();

    int row = blockIdx.x * 256 + tid;
    const float4* w = reinterpret_cast<const float4*>(Wr + (size_t)row * HR);
    float acc = 0.f;
    #pragma unroll
    for (int i = 0; i < HR / 4; ++i) {
        float4 a = w[i];
        acc += a.x * h[4 * i] + a.y * h[4 * i + 1] + a.z * h[4 * i + 2] + a.w * h[4 * i + 3];
    }
    // logits are tiny (weights ~N(0,0.05^2)); exp without max-shift is exact math
    float v = expf(acc + br[row]);
    out[row] = v;

    float s = v;
    for (int o = 16; o; o >>= 1) s += __shfl_down_sync(0xffffffffu, s, o);
    if ((tid & 31) == 0) red[tid >> 5] = s;
    __syncthreads();
    if ((tid >> 5) == 0) {
        float t2 = (tid < 8) ? red[tid] : 0.f;
        for (int o = 4; o; o >>= 1) t2 += __shfl_down_sync(0xffffffffu, t2, o);
        if (tid == 0) g_part[blockIdx.x] = t2;
    }
}

// ---------------- kernel 4: deterministic total sum -> 1/sum ---------------
__global__ void sum_kernel() {
    __shared__ float red[8];
    int tid = threadIdx.x;
    float s = g_part[tid] + g_part[tid + 256] + g_part[tid + 512] + g_part[tid + 768];
    for (int o = 16; o; o >>= 1) s += __shfl_down_sync(0xffffffffu, s, o);
    if ((tid & 31) == 0) red[tid >> 5] = s;
    __syncthreads();
    if ((tid >> 5) == 0) {
        float t2 = (tid < 8) ? red[tid] : 0.f;
        for (int o = 4; o; o >>= 1) t2 += __shfl_down_sync(0xffffffffu, t2, o);
        if (tid == 0) g_inv_d = 1.0f / t2;
    }
}

// ---------------- kernel 5: normalize ----------------
__global__ void __launch_bounds__(256)
scale_kernel(float* __restrict__ out) {
    int i = blockIdx.x * 256 + threadIdx.x;
    out[i] *= g_inv_d;
}

// ---------------- launch ----------------
extern "C" void kernel_launch(void* const* d_in, const int* in_sizes, int n_in,
                              void* d_out, int out_size) {
    const float* x     = (const float*)d_in[0];
    const float* gum   = (const float*)d_in[1];
    const float* Ws1   = (const float*)d_in[2];
    const float* bs1   = (const float*)d_in[3];
    const float* Wih1  = (const float*)d_in[4];
    const float* Whh1  = (const float*)d_in[5];
    const float* bih1  = (const float*)d_in[6];
    const float* bhh1  = (const float*)d_in[7];
    const float* Wp    = (const float*)d_in[8];
    const float* bp    = (const float*)d_in[9];
    const float* Wih2  = (const float*)d_in[10];
    const float* Whh2  = (const float*)d_in[11];
    const float* bih2  = (const float*)d_in[12];
    const float* bhh2  = (const float*)d_in[13];
    const float* Wr    = (const float*)d_in[14];
    const float* br    = (const float*)d_in[15];
    float* out = (float*)d_out;

    cudaFuncSetAttribute(seq_kernel, cudaFuncAttributeMaxDynamicSharedMemorySize,
                         SMEM_BYTES);

    h0_kernel<<<HS, 256>>>(Ws1, bs1, x);
    seq_kernel<<<8, 256, SMEM_BYTES>>>(gum, Wih1, Whh1, bih1, bhh1, Wp, bp,
                                       Wih2, Whh2, bih2, bhh2);
    out_kernel<<<OUT_N / 256, 256>>>(Wr, br, out);
    sum_kernel<<<1, 256>>>();
    scale_kernel<<<OUT_N / 256, 256>>>(out);
}